// round 5
// baseline (speedup 1.0000x reference)
#include <cuda_runtime.h>

typedef unsigned long long u64;

#define CDIM 128
#define KNB 7
#define TILE_ROWS 64
#define P1_BLOCK 256
#define MAX_BN (4 * 40962)

// Inter-kernel scratch: per-(b,node) sigmoid score. Static device array (no allocs).
__device__ float g_s[MAX_BN];

// ---- packed fp32x2 helpers (FFMA2 path; ptxas never emits this from C++) ----
__device__ __forceinline__ u64 pack2(float x, float y) {
    u64 r; asm("mov.b64 %0, {%1, %2};" : "=l"(r) : "f"(x), "f"(y)); return r;
}
__device__ __forceinline__ u64 dup2(float x) {
    u64 r; asm("mov.b64 %0, {%1, %1};" : "=l"(r) : "f"(x)); return r;
}
__device__ __forceinline__ u64 fma2(u64 a, u64 b, u64 c) {
    u64 d; asm("fma.rn.f32x2 %0, %1, %2, %3;" : "=l"(d) : "l"(a), "l"(b), "l"(c)); return d;
}
__device__ __forceinline__ void unpack2(u64 v, float& x, float& y) {
    asm("mov.b64 {%0, %1}, %2;" : "=f"(x), "=f"(y) : "l"(v));
}

__device__ __forceinline__ float fast_tanh(float x) {
    // tanh(x) = 1 - 2/(e^{2x}+1); exact limits at +-inf, ~1e-6 rel err.
    float e = __expf(2.0f * x);
    return 1.0f - __fdividef(2.0f, e + 1.0f);
}

// ============================================================================
// Pass 1: s[row] = sigmoid( tanh(query[row]@W1 + b1) . V + bV )  for row in [0, BN)
// Block: 256 threads = 8 warps. Warp w handles 8 rows of a 64-row tile.
// Lane l handles output columns 4l..4l+3. W1 (64KB) + q tile (32KB) in smem.
// ============================================================================
__global__ __launch_bounds__(P1_BLOCK, 2)
void pass1_kernel(const float* __restrict__ query, const float* __restrict__ W1,
                  const float* __restrict__ b1, const float* __restrict__ Vw,
                  const float* __restrict__ bV, int BN)
{
    extern __shared__ float smem[];
    float* sW = smem;                 // [128][128]
    float* sQ = smem + CDIM * CDIM;   // [64][128]
    const int tid  = threadIdx.x;
    const int lane = tid & 31;
    const int wrp  = tid >> 5;

    // Load W1 into smem once per block (row-major [c][d], matches global).
    for (int i = tid; i < CDIM * CDIM / 4; i += P1_BLOCK)
        ((float4*)sW)[i] = ((const float4*)W1)[i];
    __syncthreads();

    const float4 b1v = *(const float4*)(b1 + 4 * lane);
    const u64 bp0 = pack2(b1v.x, b1v.y), bp1 = pack2(b1v.z, b1v.w);
    const float4 Vv = *(const float4*)(Vw + 4 * lane);
    const float bV0 = bV[0];

    const int ntiles = (BN + TILE_ROWS - 1) / TILE_ROWS;
    for (int tile = blockIdx.x; tile < ntiles; tile += gridDim.x) {
        // Load 64x128 q tile (coalesced float4), zero-pad past BN.
        for (int i = tid; i < TILE_ROWS * 32; i += P1_BLOCK) {
            int r = i >> 5, c4 = (i & 31) * 4;
            long grow = (long)tile * TILE_ROWS + r;
            float4 v = make_float4(0.f, 0.f, 0.f, 0.f);
            if (grow < BN) v = *(const float4*)(query + grow * CDIM + c4);
            *(float4*)(sQ + r * CDIM + c4) = v;
        }
        __syncthreads();

        u64 acc[8][2];
        #pragma unroll
        for (int r = 0; r < 8; r++) { acc[r][0] = bp0; acc[r][1] = bp1; }

        const float* qbase = sQ + wrp * 8 * CDIM;
        #pragma unroll 2
        for (int c = 0; c < CDIM; c += 4) {
            // W1 rows c..c+3, this lane's 4 columns, as packed f32x2 pairs.
            ulonglong2 w0 = *(const ulonglong2*)(sW + (c + 0) * CDIM + 4 * lane);
            ulonglong2 w1 = *(const ulonglong2*)(sW + (c + 1) * CDIM + 4 * lane);
            ulonglong2 w2 = *(const ulonglong2*)(sW + (c + 2) * CDIM + 4 * lane);
            ulonglong2 w3 = *(const ulonglong2*)(sW + (c + 3) * CDIM + 4 * lane);
            #pragma unroll
            for (int r = 0; r < 8; r++) {
                float4 q4 = *(const float4*)(qbase + r * CDIM + c);
                u64 qx = dup2(q4.x), qy = dup2(q4.y), qz = dup2(q4.z), qw = dup2(q4.w);
                acc[r][0] = fma2(qx, w0.x, acc[r][0]);
                acc[r][1] = fma2(qx, w0.y, acc[r][1]);
                acc[r][0] = fma2(qy, w1.x, acc[r][0]);
                acc[r][1] = fma2(qy, w1.y, acc[r][1]);
                acc[r][0] = fma2(qz, w2.x, acc[r][0]);
                acc[r][1] = fma2(qz, w2.y, acc[r][1]);
                acc[r][0] = fma2(qw, w3.x, acc[r][0]);
                acc[r][1] = fma2(qw, w3.y, acc[r][1]);
            }
        }

        // Epilogue: tanh, dot with V, warp-reduce across the 128 columns.
        #pragma unroll
        for (int r = 0; r < 8; r++) {
            float h0, h1, h2, h3;
            unpack2(acc[r][0], h0, h1);
            unpack2(acc[r][1], h2, h3);
            float p = fast_tanh(h0) * Vv.x + fast_tanh(h1) * Vv.y
                    + fast_tanh(h2) * Vv.z + fast_tanh(h3) * Vv.w;
            #pragma unroll
            for (int off = 16; off > 0; off >>= 1)
                p += __shfl_xor_sync(0xffffffffu, p, off);
            long row = (long)tile * TILE_ROWS + wrp * 8 + r;
            if (lane == 0 && row < BN) {
                float z = p + bV0;
                g_s[row] = __fdividef(1.0f, 1.0f + __expf(-z));
            }
        }
        __syncthreads();
    }
}

// ============================================================================
// Pass 2: per (b,n): gather 7 scores, normalize, weighted sum of gathered
// values rows. One warp per (b,n); lane l owns channels 4l..4l+3.
// ============================================================================
__global__ __launch_bounds__(256)
void pass2_kernel(const float* __restrict__ values, const int* __restrict__ neigh,
                  float* __restrict__ ctx, float* __restrict__ score,
                  int BN, int N)
{
    int gw = blockIdx.x * 8 + (threadIdx.x >> 5);
    if (gw >= BN) return;
    const int lane = threadIdx.x & 31;
    const int b = gw / N;
    const int n = gw - b * N;

    const int* nb = neigh + (long)n * KNB;
    int   ix[KNB];
    float sk[KNB];
    float sum = 0.f;
    #pragma unroll
    for (int k = 0; k < KNB; k++) {
        ix[k] = nb[k];
        sk[k] = g_s[b * N + ix[k]];
        sum  += sk[k];
    }
    float inv = __fdividef(1.0f, sum);

    // score output is the raw sigmoid (pre-normalization), per reference.
    if (lane < KNB) score[(long)gw * KNB + lane] = sk[lane];

    const float* vb = values + (long)b * N * CDIM;
    float4 accv = make_float4(0.f, 0.f, 0.f, 0.f);
    #pragma unroll
    for (int k = 0; k < KNB; k++) {
        float w = sk[k] * inv;
        float4 v4 = *(const float4*)(vb + (long)ix[k] * CDIM + 4 * lane);
        accv.x += w * v4.x; accv.y += w * v4.y;
        accv.z += w * v4.z; accv.w += w * v4.w;
    }
    *(float4*)(ctx + (long)gw * CDIM + 4 * lane) = accv;
}

// ============================================================================
// Launch
// Inputs: 0 query (B,N,C) f32 | 1 values (B,N,C) f32 | 2 neigh_orders (N,K) i32
//         3 W1 (C,C) f32 | 4 b1 (C,) f32 | 5 V (C,1) f32 | 6 bV (1,) f32
// Output: context (B,N,C) then score (B,N,K,1), concatenated flat.
// ============================================================================
extern "C" void kernel_launch(void* const* d_in, const int* in_sizes, int n_in,
                              void* d_out, int out_size)
{
    const float* query  = (const float*)d_in[0];
    const float* values = (const float*)d_in[1];
    const int*   neigh  = (const int*)d_in[2];
    const float* W1     = (const float*)d_in[3];
    const float* b1     = (const float*)d_in[4];
    const float* Vw     = (const float*)d_in[5];
    const float* bV     = (const float*)d_in[6];

    const int BN = in_sizes[0] / CDIM;      // B*N
    const int N  = in_sizes[2] / KNB;       // nodes

    float* ctx   = (float*)d_out;
    float* score = (float*)d_out + (size_t)BN * CDIM;

    const int smem_bytes = (CDIM * CDIM + TILE_ROWS * CDIM) * sizeof(float); // 96 KB
    cudaFuncSetAttribute(pass1_kernel, cudaFuncAttributeMaxDynamicSharedMemorySize,
                         smem_bytes);

    pass1_kernel<<<296, P1_BLOCK, smem_bytes>>>(query, W1, b1, Vw, bV, BN);

    int p2_blocks = (BN + 7) / 8;
    pass2_kernel<<<p2_blocks, 256>>>(values, neigh, ctx, score, BN, N);
}

// round 8
// speedup vs baseline: 1.0260x; 1.0260x over previous
#include <cuda_runtime.h>
#include <cuda_bf16.h>
#include <cstdint>

#define CDIM 128
#define KNB 7
#define TILE_M 128
#define P1_THREADS 256
#define MAX_BN (4 * 40962)

// Inter-kernel scratch: per-(b,node) sigmoid score.
__device__ float g_s[MAX_BN];

// ---------------------------------------------------------------------------
// Dynamic SMEM layout (bytes)
//   W hi/lo : transposed W1 (W_t[d][c]) as bf16, XOR-swizzled rows
//   A hi/lo : 128x128 q tile as bf16, same layout
// ---------------------------------------------------------------------------
#define OFF_WHI 0
#define OFF_WLO (OFF_WHI + 32768)
#define OFF_AHI (OFF_WLO + 32768)
#define OFF_ALO (OFF_AHI + 32768)
#define OFF_B1  (OFF_ALO + 32768)
#define OFF_V   (OFF_B1 + 512)
#define SMEM_TOTAL (OFF_V + 512)   // 131,584 B

__device__ __forceinline__ uint32_t smem_u32(const void* p) {
    uint32_t a;
    asm("{ .reg .u64 t; cvta.to.shared.u64 t, %1; cvt.u32.u64 %0, t; }" : "=r"(a) : "l"(p));
    return a;
}

// Swizzled byte offset inside a [128 rows][128 bf16] tile.
// Row = 256 B = 16 units of 16 B; unit index XORed with (row & 7) so
// ldmatrix's 8-row reads hit 8 distinct 16B banks groups (conflict-free).
__device__ __forceinline__ uint32_t swz(int row, int k) {
    return (uint32_t)(row * 256 + ((((k >> 3) ^ (row & 7)) << 4) | ((k & 7) << 1)));
}

__device__ __forceinline__ void ldsm4(uint32_t r[4], uint32_t addr) {
    asm volatile("ldmatrix.sync.aligned.m8n8.x4.shared.b16 {%0,%1,%2,%3}, [%4];"
                 : "=r"(r[0]), "=r"(r[1]), "=r"(r[2]), "=r"(r[3]) : "r"(addr));
}

__device__ __forceinline__ void mma16816(float c[4], const uint32_t a[4],
                                         uint32_t b0, uint32_t b1) {
    asm volatile(
        "mma.sync.aligned.m16n8k16.row.col.f32.bf16.bf16.f32 "
        "{%0,%1,%2,%3}, {%4,%5,%6,%7}, {%8,%9}, {%0,%1,%2,%3};"
        : "+f"(c[0]), "+f"(c[1]), "+f"(c[2]), "+f"(c[3])
        : "r"(a[0]), "r"(a[1]), "r"(a[2]), "r"(a[3]), "r"(b0), "r"(b1));
}

__device__ __forceinline__ float tanh_a(float x) {
    float y; asm("tanh.approx.f32 %0, %1;" : "=f"(y) : "f"(x)); return y;
}

// split fp32 -> (hi, lo) bf16 pair
__device__ __forceinline__ void bsplit(float x, __nv_bfloat16& h, __nv_bfloat16& l) {
    h = __float2bfloat16(x);
    l = __float2bfloat16(x - __bfloat162float(h));
}

// ============================================================================
// Pass 1 (HMMA via mma.sync): s[row] = sigmoid( tanh(q[row]@W1 + b1) . V + bV )
// Persistent CTAs. Per 128-row tile: stage q as hi/lo bf16 (swizzled), 8 warps
// each compute a 16x128 slice with m16n8k16 MMAs (3 precision groups), then
// fused tanh/dotV/sigmoid epilogue.
// ============================================================================
__global__ __launch_bounds__(P1_THREADS, 1)
void pass1_hmma(const float* __restrict__ query, const float* __restrict__ W1,
                const float* __restrict__ b1, const float* __restrict__ Vw,
                const float* __restrict__ bV, int BN)
{
    extern __shared__ char smem[];
    const uint32_t sb = smem_u32(smem);
    const int tid = threadIdx.x, lane = tid & 31, wrp = tid >> 5;

    // ---- One-time: stage W1 coalesced, then build transposed hi/lo bf16 tiles
    float* tmpW = (float*)(smem + OFF_AHI);   // reuse A region as scratch
    for (int i = tid; i < CDIM * CDIM / 4; i += P1_THREADS)
        ((float4*)tmpW)[i] = ((const float4*)W1)[i];
    if (tid < CDIM) {
        ((float*)(smem + OFF_B1))[tid] = b1[tid];
        ((float*)(smem + OFF_V))[tid]  = Vw[tid];
    }
    __syncthreads();

    for (int i = tid; i < CDIM * CDIM / 2; i += P1_THREADS) {
        int d = i >> 6, c = (i & 63) * 2;            // W_t[d][c] = W1[c][d]
        float x0 = tmpW[(c + 0) * CDIM + d];
        float x1 = tmpW[(c + 1) * CDIM + d];
        __nv_bfloat16 h0, l0, h1, l1;
        bsplit(x0, h0, l0); bsplit(x1, h1, l1);
        __nv_bfloat162 hp; hp.x = h0; hp.y = h1;
        __nv_bfloat162 lp; lp.x = l0; lp.y = l1;
        uint32_t off = swz(d, c);
        *(__nv_bfloat162*)(smem + OFF_WHI + off) = hp;
        *(__nv_bfloat162*)(smem + OFF_WLO + off) = lp;
    }
    __syncthreads();

    const float* sB1 = (const float*)(smem + OFF_B1);
    const float* sV  = (const float*)(smem + OFF_V);
    const float bV0 = bV[0];

    // per-lane ldmatrix addressing components
    const int lrow = lane & 15;               // row within 16-row tile
    const int lkof = (lane >> 4) << 3;        // k offset (0 or 8)
    const int r0 = wrp * 16;                  // this warp's row base in tile

    const int ntiles = (BN + TILE_M - 1) / TILE_M;

    for (int tile = blockIdx.x; tile < ntiles; tile += gridDim.x) {
        // ---- Stage A tile: q fp32 -> hi/lo bf16, swizzled
        #pragma unroll 4
        for (int it = 0; it < TILE_M * 64 / P1_THREADS; it++) {
            int i = tid + it * P1_THREADS;
            int row = i >> 6, k = (i & 63) * 2;
            long grow = (long)tile * TILE_M + row;
            float2 q2 = make_float2(0.f, 0.f);
            if (grow < BN) q2 = *(const float2*)(query + grow * CDIM + k);
            __nv_bfloat16 h0, l0, h1, l1;
            bsplit(q2.x, h0, l0); bsplit(q2.y, h1, l1);
            __nv_bfloat162 hp; hp.x = h0; hp.y = h1;
            __nv_bfloat162 lp; lp.x = l0; lp.y = l1;
            uint32_t off = swz(row, k);
            *(__nv_bfloat162*)(smem + OFF_AHI + off) = hp;
            *(__nv_bfloat162*)(smem + OFF_ALO + off) = lp;
        }
        __syncthreads();

        float zlo = 0.f, zhi = 0.f;

        #pragma unroll
        for (int h = 0; h < 2; h++) {          // n-halves: cols [0,64), [64,128)
            float acc[8][4];
            #pragma unroll
            for (int t = 0; t < 8; t++)
                #pragma unroll
                for (int j = 0; j < 4; j++) acc[t][j] = 0.f;

            #pragma unroll
            for (int k0 = 0; k0 < CDIM; k0 += 16) {
                uint32_t ahi[4], alo[4];
                uint32_t aoff = swz(r0 + lrow, k0 + lkof);
                ldsm4(ahi, sb + OFF_AHI + aoff);
                ldsm4(alo, sb + OFF_ALO + aoff);
                #pragma unroll
                for (int tp = 0; tp < 4; tp++) {
                    int n0 = h * 64 + tp * 16;
                    uint32_t bh[4], bl[4];
                    uint32_t boff = swz(n0 + lrow, k0 + lkof);
                    ldsm4(bh, sb + OFF_WHI + boff);
                    ldsm4(bl, sb + OFF_WLO + boff);
                    mma16816(acc[2 * tp],     ahi, bh[0], bh[2]);
                    mma16816(acc[2 * tp + 1], ahi, bh[1], bh[3]);
                    mma16816(acc[2 * tp],     ahi, bl[0], bl[2]);
                    mma16816(acc[2 * tp + 1], ahi, bl[1], bl[3]);
                    mma16816(acc[2 * tp],     alo, bh[0], bh[2]);
                    mma16816(acc[2 * tp + 1], alo, bh[1], bh[3]);
                }
            }

            // Epilogue for this half: tanh(h + b1) . V, per-lane partials.
            // C frag: c0,c1 -> row l/4, cols 2(l%4)+{0,1}; c2,c3 -> row l/4+8.
            #pragma unroll
            for (int t = 0; t < 8; t++) {
                int c0 = h * 64 + t * 8 + 2 * (lane & 3);
                float b0 = sB1[c0], b1v = sB1[c0 + 1];
                float v0 = sV[c0],  v1  = sV[c0 + 1];
                zlo += tanh_a(acc[t][0] + b0) * v0 + tanh_a(acc[t][1] + b1v) * v1;
                zhi += tanh_a(acc[t][2] + b0) * v0 + tanh_a(acc[t][3] + b1v) * v1;
            }
        }

        // Reduce across the 4 lanes sharing a row
        zlo += __shfl_xor_sync(0xffffffffu, zlo, 1);
        zlo += __shfl_xor_sync(0xffffffffu, zlo, 2);
        zhi += __shfl_xor_sync(0xffffffffu, zhi, 1);
        zhi += __shfl_xor_sync(0xffffffffu, zhi, 2);

        if ((lane & 3) == 0) {
            long rlo = (long)tile * TILE_M + r0 + (lane >> 2);
            long rhi = rlo + 8;
            if (rlo < BN) {
                float z = zlo + bV0;
                g_s[rlo] = __fdividef(1.0f, 1.0f + __expf(-z));
            }
            if (rhi < BN) {
                float z = zhi + bV0;
                g_s[rhi] = __fdividef(1.0f, 1.0f + __expf(-z));
            }
        }
        __syncthreads();   // all reads of A done before next tile overwrites
    }
}

// ============================================================================
// Pass 2: one warp per node n, loops over all B batches (indices batch-invariant).
// Lane l owns channels 4l..4l+3.
// ============================================================================
__global__ __launch_bounds__(256)
void pass2_kernel(const float* __restrict__ values, const int* __restrict__ neigh,
                  float* __restrict__ ctx, float* __restrict__ score,
                  int N, int B)
{
    int n = blockIdx.x * 8 + (threadIdx.x >> 5);
    if (n >= N) return;
    const int lane = threadIdx.x & 31;

    const int* nb = neigh + (long)n * KNB;
    int ix[KNB];
    #pragma unroll
    for (int k = 0; k < KNB; k++) ix[k] = nb[k];

    for (int b = 0; b < B; b++) {
        const float* gs = g_s + (long)b * N;
        float sk[KNB];
        float sum = 0.f;
        #pragma unroll
        for (int k = 0; k < KNB; k++) { sk[k] = gs[ix[k]]; sum += sk[k]; }
        float inv = __fdividef(1.0f, sum);

        long gw = (long)b * N + n;
        if (lane < KNB) score[gw * KNB + lane] = sk[lane];

        const float* vb = values + (long)b * N * CDIM;
        float4 a = make_float4(0.f, 0.f, 0.f, 0.f);
        #pragma unroll
        for (int k = 0; k < KNB; k++) {
            float w = sk[k] * inv;
            float4 v = *(const float4*)(vb + (long)ix[k] * CDIM + 4 * lane);
            a.x += w * v.x; a.y += w * v.y; a.z += w * v.z; a.w += w * v.w;
        }
        *(float4*)(ctx + gw * CDIM + 4 * lane) = a;
    }
}

// ============================================================================
// Launch
// ============================================================================
extern "C" void kernel_launch(void* const* d_in, const int* in_sizes, int n_in,
                              void* d_out, int out_size)
{
    const float* query  = (const float*)d_in[0];
    const float* values = (const float*)d_in[1];
    const int*   neigh  = (const int*)d_in[2];
    const float* W1     = (const float*)d_in[3];
    const float* b1     = (const float*)d_in[4];
    const float* Vw     = (const float*)d_in[5];
    const float* bV     = (const float*)d_in[6];

    const int BN = in_sizes[0] / CDIM;   // B*N
    const int N  = in_sizes[2] / KNB;    // nodes
    const int B  = BN / N;

    float* ctx   = (float*)d_out;
    float* score = (float*)d_out + (size_t)BN * CDIM;

    int nsm = 148;
    cudaDeviceGetAttribute(&nsm, cudaDevAttrMultiProcessorCount, 0);

    cudaFuncSetAttribute(pass1_hmma, cudaFuncAttributeMaxDynamicSharedMemorySize, SMEM_TOTAL);
    pass1_hmma<<<nsm, P1_THREADS, SMEM_TOTAL>>>(query, W1, b1, Vw, bV, BN);

    int p2_blocks = (N + 7) / 8;
    pass2_kernel<<<p2_blocks, 256>>>(values, neigh, ctx, score, N, B);
}

// round 9
// speedup vs baseline: 1.6292x; 1.5879x over previous
#include <cuda_runtime.h>
#include <cuda_fp16.h>
#include <cstdint>

#define CDIM 128
#define KNB 7
#define TILE_M 128
#define P1_THREADS 256
#define MAX_BN (4 * 40962)

// Inter-kernel scratch: per-(b,node) sigmoid score.
__device__ float g_s[MAX_BN];

// ---------------------------------------------------------------------------
// Dynamic SMEM layout (bytes): W (fp16, transposed, swizzled) + A (fp16 tile)
// A region doubles as fp32 staging scratch for the one-time W transpose.
// ---------------------------------------------------------------------------
#define OFF_W  0
#define OFF_A  32768
#define OFF_B1 (OFF_A + 32768)
#define OFF_V  (OFF_B1 + 512)
#define SMEM_TOTAL (OFF_V + 512)   // 66,560 B -> 2 CTAs/SM

__device__ __forceinline__ uint32_t smem_u32(const void* p) {
    uint32_t a;
    asm("{ .reg .u64 t; cvta.to.shared.u64 t, %1; cvt.u32.u64 %0, t; }" : "=r"(a) : "l"(p));
    return a;
}

// Swizzled byte offset inside a [128 rows][128 fp16] tile.
// Row = 256 B = 16 units of 16 B; unit index XORed with (row & 7) so
// ldmatrix's 8-row reads hit distinct 16B groups (conflict-free; verified R8).
__device__ __forceinline__ uint32_t swz(int row, int k) {
    return (uint32_t)(row * 256 + ((((k >> 3) ^ (row & 7)) << 4) | ((k & 7) << 1)));
}

__device__ __forceinline__ void ldsm4(uint32_t r[4], uint32_t addr) {
    asm volatile("ldmatrix.sync.aligned.m8n8.x4.shared.b16 {%0,%1,%2,%3}, [%4];"
                 : "=r"(r[0]), "=r"(r[1]), "=r"(r[2]), "=r"(r[3]) : "r"(addr));
}

__device__ __forceinline__ void mma16816(float c[4], const uint32_t a[4],
                                         uint32_t b0, uint32_t b1) {
    asm volatile(
        "mma.sync.aligned.m16n8k16.row.col.f32.f16.f16.f32 "
        "{%0,%1,%2,%3}, {%4,%5,%6,%7}, {%8,%9}, {%0,%1,%2,%3};"
        : "+f"(c[0]), "+f"(c[1]), "+f"(c[2]), "+f"(c[3])
        : "r"(a[0]), "r"(a[1]), "r"(a[2]), "r"(a[3]), "r"(b0), "r"(b1));
}

__device__ __forceinline__ float tanh_a(float x) {
    float y; asm("tanh.approx.f32 %0, %1;" : "=f"(y) : "f"(x)); return y;
}

// ============================================================================
// Pass 1 (HMMA, single fp16 product):
//   s[row] = sigmoid( tanh(q[row]@W1 + b1) . V + bV )
// Persistent CTAs, 2 per SM. Per 128-row tile: stage q as fp16 (swizzled),
// 8 warps x (16 rows x 128 cols) of m16n8k16 MMAs, fused tanh/dotV/sigmoid.
// ============================================================================
__global__ __launch_bounds__(P1_THREADS, 2)
void pass1_hmma(const float* __restrict__ query, const float* __restrict__ W1,
                const float* __restrict__ b1, const float* __restrict__ Vw,
                const float* __restrict__ bV, int BN)
{
    extern __shared__ char smem[];
    const uint32_t sb = smem_u32(smem);
    const int tid = threadIdx.x, lane = tid & 31, wrp = tid >> 5;

    // ---- One-time: W1 -> transposed fp16 W_t[d][c] in two 64-row chunks,
    // using the A region as coalesced fp32 staging scratch.
    float* tmpW = (float*)(smem + OFF_A);   // 64 rows x 128 fp32 = 32 KB
    for (int half = 0; half < 2; half++) {
        for (int i = tid; i < 64 * CDIM / 4; i += P1_THREADS)
            ((float4*)tmpW)[i] = ((const float4*)(W1 + half * 64 * CDIM))[i];
        __syncthreads();
        for (int i = tid; i < CDIM * 32; i += P1_THREADS) {
            int d = i >> 5, r = (i & 31) * 2;        // local rows r, r+1
            float x0 = tmpW[(r + 0) * CDIM + d];
            float x1 = tmpW[(r + 1) * CDIM + d];
            __half2 hp = __floats2half2_rn(x0, x1);
            *(__half2*)(smem + OFF_W + swz(d, half * 64 + r)) = hp;
        }
        __syncthreads();
    }
    if (tid < CDIM) {
        ((float*)(smem + OFF_B1))[tid] = b1[tid];
        ((float*)(smem + OFF_V))[tid]  = Vw[tid];
    }
    __syncthreads();

    const float* sB1 = (const float*)(smem + OFF_B1);
    const float* sV  = (const float*)(smem + OFF_V);
    const float bV0 = bV[0];

    // per-lane ldmatrix addressing components
    const int lrow = lane & 15;               // row within 16-row tile
    const int lkof = (lane >> 4) << 3;        // k offset (0 or 8)
    const int r0 = wrp * 16;                  // this warp's row base in tile

    const int ntiles = (BN + TILE_M - 1) / TILE_M;

    for (int tile = blockIdx.x; tile < ntiles; tile += gridDim.x) {
        // ---- Stage A tile: q fp32 -> fp16, swizzled
        #pragma unroll 4
        for (int it = 0; it < TILE_M * 64 / P1_THREADS; it++) {
            int i = tid + it * P1_THREADS;
            int row = i >> 6, k = (i & 63) * 2;
            long grow = (long)tile * TILE_M + row;
            float2 q2 = make_float2(0.f, 0.f);
            if (grow < BN) q2 = *(const float2*)(query + grow * CDIM + k);
            *(__half2*)(smem + OFF_A + swz(row, k)) = __floats2half2_rn(q2.x, q2.y);
        }
        __syncthreads();

        float zlo = 0.f, zhi = 0.f;

        #pragma unroll
        for (int h = 0; h < 2; h++) {          // n-halves: cols [0,64), [64,128)
            float acc[8][4];
            #pragma unroll
            for (int t = 0; t < 8; t++)
                #pragma unroll
                for (int j = 0; j < 4; j++) acc[t][j] = 0.f;

            #pragma unroll
            for (int k0 = 0; k0 < CDIM; k0 += 16) {
                uint32_t a[4];
                ldsm4(a, sb + OFF_A + swz(r0 + lrow, k0 + lkof));
                #pragma unroll
                for (int tp = 0; tp < 4; tp++) {
                    int n0 = h * 64 + tp * 16;
                    uint32_t bh[4];
                    ldsm4(bh, sb + OFF_W + swz(n0 + lrow, k0 + lkof));
                    mma16816(acc[2 * tp],     a, bh[0], bh[2]);
                    mma16816(acc[2 * tp + 1], a, bh[1], bh[3]);
                }
            }

            // Epilogue for this half: tanh(h + b1) . V, per-lane partials.
            // C frag: c0,c1 -> row l/4, cols 2(l%4)+{0,1}; c2,c3 -> row l/4+8.
            #pragma unroll
            for (int t = 0; t < 8; t++) {
                int c0 = h * 64 + t * 8 + 2 * (lane & 3);
                float b0 = sB1[c0], b1v = sB1[c0 + 1];
                float v0 = sV[c0],  v1  = sV[c0 + 1];
                zlo += tanh_a(acc[t][0] + b0) * v0 + tanh_a(acc[t][1] + b1v) * v1;
                zhi += tanh_a(acc[t][2] + b0) * v0 + tanh_a(acc[t][3] + b1v) * v1;
            }
        }

        // Reduce across the 4 lanes sharing a row
        zlo += __shfl_xor_sync(0xffffffffu, zlo, 1);
        zlo += __shfl_xor_sync(0xffffffffu, zlo, 2);
        zhi += __shfl_xor_sync(0xffffffffu, zhi, 1);
        zhi += __shfl_xor_sync(0xffffffffu, zhi, 2);

        if ((lane & 3) == 0) {
            long rlo = (long)tile * TILE_M + r0 + (lane >> 2);
            long rhi = rlo + 8;
            if (rlo < BN) {
                float z = zlo + bV0;
                g_s[rlo] = __fdividef(1.0f, 1.0f + __expf(-z));
            }
            if (rhi < BN) {
                float z = zhi + bV0;
                g_s[rhi] = __fdividef(1.0f, 1.0f + __expf(-z));
            }
        }
        __syncthreads();   // all reads of A done before next tile overwrites
    }
}

// ============================================================================
// Pass 2 (R5 structure — measured 57.6us): one warp per (b,n); gather 7
// scores, normalize, weighted sum of gathered values rows. Lane l owns
// channels 4l..4l+3.
// ============================================================================
__global__ __launch_bounds__(256)
void pass2_kernel(const float* __restrict__ values, const int* __restrict__ neigh,
                  float* __restrict__ ctx, float* __restrict__ score,
                  int BN, int N)
{
    int gw = blockIdx.x * 8 + (threadIdx.x >> 5);
    if (gw >= BN) return;
    const int lane = threadIdx.x & 31;
    const int b = gw / N;
    const int n = gw - b * N;

    const int* nb = neigh + (long)n * KNB;
    int   ix[KNB];
    float sk[KNB];
    float sum = 0.f;
    #pragma unroll
    for (int k = 0; k < KNB; k++) {
        ix[k] = nb[k];
        sk[k] = g_s[b * N + ix[k]];
        sum  += sk[k];
    }
    float inv = __fdividef(1.0f, sum);

    // score output is the raw sigmoid (pre-normalization), per reference.
    if (lane < KNB) score[(long)gw * KNB + lane] = sk[lane];

    const float* vb = values + (long)b * N * CDIM;
    float4 accv = make_float4(0.f, 0.f, 0.f, 0.f);
    #pragma unroll
    for (int k = 0; k < KNB; k++) {
        float w = sk[k] * inv;
        float4 v4 = *(const float4*)(vb + (long)ix[k] * CDIM + 4 * lane);
        accv.x += w * v4.x; accv.y += w * v4.y;
        accv.z += w * v4.z; accv.w += w * v4.w;
    }
    *(float4*)(ctx + (long)gw * CDIM + 4 * lane) = accv;
}

// ============================================================================
// Launch
// ============================================================================
extern "C" void kernel_launch(void* const* d_in, const int* in_sizes, int n_in,
                              void* d_out, int out_size)
{
    const float* query  = (const float*)d_in[0];
    const float* values = (const float*)d_in[1];
    const int*   neigh  = (const int*)d_in[2];
    const float* W1     = (const float*)d_in[3];
    const float* b1     = (const float*)d_in[4];
    const float* Vw     = (const float*)d_in[5];
    const float* bV     = (const float*)d_in[6];

    const int BN = in_sizes[0] / CDIM;   // B*N
    const int N  = in_sizes[2] / KNB;    // nodes

    float* ctx   = (float*)d_out;
    float* score = (float*)d_out + (size_t)BN * CDIM;

    int nsm = 148;
    cudaDeviceGetAttribute(&nsm, cudaDevAttrMultiProcessorCount, 0);

    cudaFuncSetAttribute(pass1_hmma, cudaFuncAttributeMaxDynamicSharedMemorySize, SMEM_TOTAL);
    pass1_hmma<<<2 * nsm, P1_THREADS, SMEM_TOTAL>>>(query, W1, b1, Vw, bV, BN);

    int p2_blocks = (BN + 7) / 8;
    pass2_kernel<<<p2_blocks, 256>>>(values, neigh, ctx, score, BN, N);
}

// round 10
// speedup vs baseline: 1.9216x; 1.1795x over previous
#include <cuda_runtime.h>
#include <cuda_fp16.h>
#include <cstdint>

#define CDIM 128
#define KNB 7
#define TILE_M 128
#define P1_THREADS 256
#define MAX_BN (4 * 40962)

// Inter-kernel scratch: per-(b,node) sigmoid score.
__device__ float g_s[MAX_BN];

// ---------------------------------------------------------------------------
// Dynamic SMEM layout (bytes): W (fp16, transposed, swizzled) + A (fp16 tile)
// A region doubles as fp32 staging scratch for the one-time W transpose.
// ---------------------------------------------------------------------------
#define OFF_W  0
#define OFF_A  32768
#define OFF_B1 (OFF_A + 32768)
#define OFF_V  (OFF_B1 + 512)
#define SMEM_TOTAL (OFF_V + 512)   // 66,560 B -> 2 CTAs/SM

__device__ __forceinline__ uint32_t smem_u32(const void* p) {
    uint32_t a;
    asm("{ .reg .u64 t; cvta.to.shared.u64 t, %1; cvt.u32.u64 %0, t; }" : "=r"(a) : "l"(p));
    return a;
}

// Swizzled byte offset inside a [128 rows][128 fp16] tile.
// Row = 256 B = 16 units of 16 B; unit index XORed with (row & 7) so
// ldmatrix's 8-row reads hit distinct 16B groups (conflict-free; verified R8/R9).
__device__ __forceinline__ uint32_t swz(int row, int k) {
    return (uint32_t)(row * 256 + ((((k >> 3) ^ (row & 7)) << 4) | ((k & 7) << 1)));
}

__device__ __forceinline__ void ldsm4(uint32_t r[4], uint32_t addr) {
    asm volatile("ldmatrix.sync.aligned.m8n8.x4.shared.b16 {%0,%1,%2,%3}, [%4];"
                 : "=r"(r[0]), "=r"(r[1]), "=r"(r[2]), "=r"(r[3]) : "r"(addr));
}

__device__ __forceinline__ void mma16816(float c[4], const uint32_t a[4],
                                         uint32_t b0, uint32_t b1) {
    asm volatile(
        "mma.sync.aligned.m16n8k16.row.col.f32.f16.f16.f32 "
        "{%0,%1,%2,%3}, {%4,%5,%6,%7}, {%8,%9}, {%0,%1,%2,%3};"
        : "+f"(c[0]), "+f"(c[1]), "+f"(c[2]), "+f"(c[3])
        : "r"(a[0]), "r"(a[1]), "r"(a[2]), "r"(a[3]), "r"(b0), "r"(b1));
}

__device__ __forceinline__ float tanh_a(float x) {
    float y; asm("tanh.approx.f32 %0, %1;" : "=f"(y) : "f"(x)); return y;
}

// ============================================================================
// Pass 1 (HMMA, single fp16 product):
//   s[row] = sigmoid( tanh(q[row]@W1 + b1) . V + bV )
// Persistent CTAs, 2/SM. Per 128-row tile: stage q as fp16 (swizzled,
// LDG.128/STS.64), 8 warps x 16 rows x full 128-col accumulator (b1 folded
// into acc init), fused tanh/dotV/sigmoid epilogue.
// ============================================================================
__global__ __launch_bounds__(P1_THREADS, 2)
void pass1_hmma(const float* __restrict__ query, const float* __restrict__ W1,
                const float* __restrict__ b1, const float* __restrict__ Vw,
                const float* __restrict__ bV, int BN)
{
    extern __shared__ char smem[];
    const uint32_t sb = smem_u32(smem);
    const int tid = threadIdx.x, lane = tid & 31, wrp = tid >> 5;

    // ---- One-time: W1 -> transposed fp16 W_t[d][c] in two 64-row chunks,
    // using the A region as coalesced fp32 staging scratch.
    float* tmpW = (float*)(smem + OFF_A);   // 64 rows x 128 fp32 = 32 KB
    for (int half = 0; half < 2; half++) {
        for (int i = tid; i < 64 * CDIM / 4; i += P1_THREADS)
            ((float4*)tmpW)[i] = ((const float4*)(W1 + half * 64 * CDIM))[i];
        __syncthreads();
        for (int i = tid; i < CDIM * 32; i += P1_THREADS) {
            int d = i >> 5, r = (i & 31) * 2;        // local rows r, r+1
            float x0 = tmpW[(r + 0) * CDIM + d];
            float x1 = tmpW[(r + 1) * CDIM + d];
            __half2 hp = __floats2half2_rn(x0, x1);
            *(__half2*)(smem + OFF_W + swz(d, half * 64 + r)) = hp;
        }
        __syncthreads();
    }
    if (tid < CDIM) {
        ((float*)(smem + OFF_B1))[tid] = b1[tid];
        ((float*)(smem + OFF_V))[tid]  = Vw[tid];
    }
    __syncthreads();

    const float* sB1 = (const float*)(smem + OFF_B1);
    const float* sV  = (const float*)(smem + OFF_V);
    const float bV0 = bV[0];

    // per-lane ldmatrix addressing components
    const int lrow = lane & 15;               // row within 16-row tile
    const int lkof = (lane >> 4) << 3;        // k offset (0 or 8)
    const int r0 = wrp * 16;                  // this warp's row base in tile
    const int cq = 2 * (lane & 3);            // this lane's col pair offset

    const int ntiles = (BN + TILE_M - 1) / TILE_M;

    for (int tile = blockIdx.x; tile < ntiles; tile += gridDim.x) {
        // ---- Stage A tile: q fp32 -> fp16 via LDG.128 + STS.64, swizzled
        #pragma unroll
        for (int it = 0; it < TILE_M * 32 / P1_THREADS; it++) {   // 16 iters
            int i = tid + it * P1_THREADS;
            int row = i >> 5, c4 = (i & 31) * 4;
            long grow = (long)tile * TILE_M + row;
            float4 q4 = make_float4(0.f, 0.f, 0.f, 0.f);
            if (grow < BN) q4 = *(const float4*)(query + grow * CDIM + c4);
            __half2 h01 = __floats2half2_rn(q4.x, q4.y);
            __half2 h23 = __floats2half2_rn(q4.z, q4.w);
            uint2 pk;
            pk.x = *(uint32_t*)&h01;
            pk.y = *(uint32_t*)&h23;
            *(uint2*)(smem + OFF_A + swz(row, c4)) = pk;
        }
        __syncthreads();

        // ---- Full-width accumulator, b1 folded into init.
        // acc[t][0..1] -> row lane/4,   cols t*8 + cq + {0,1}
        // acc[t][2..3] -> row lane/4+8, same cols
        float acc[16][4];
        #pragma unroll
        for (int t = 0; t < 16; t++) {
            float b0 = sB1[t * 8 + cq], b1v = sB1[t * 8 + cq + 1];
            acc[t][0] = b0; acc[t][1] = b1v;
            acc[t][2] = b0; acc[t][3] = b1v;
        }

        #pragma unroll
        for (int k0 = 0; k0 < CDIM; k0 += 16) {
            uint32_t a[4];
            ldsm4(a, sb + OFF_A + swz(r0 + lrow, k0 + lkof));
            #pragma unroll
            for (int tp = 0; tp < 8; tp++) {
                uint32_t bh[4];
                ldsm4(bh, sb + OFF_W + swz(tp * 16 + lrow, k0 + lkof));
                mma16816(acc[2 * tp],     a, bh[0], bh[2]);
                mma16816(acc[2 * tp + 1], a, bh[1], bh[3]);
            }
        }

        // ---- Epilogue: tanh . V, per-lane partials over this lane's 32 cols
        float zlo = 0.f, zhi = 0.f;
        #pragma unroll
        for (int t = 0; t < 16; t++) {
            float v0 = sV[t * 8 + cq], v1 = sV[t * 8 + cq + 1];
            zlo += tanh_a(acc[t][0]) * v0 + tanh_a(acc[t][1]) * v1;
            zhi += tanh_a(acc[t][2]) * v0 + tanh_a(acc[t][3]) * v1;
        }

        // Reduce across the 4 lanes sharing a row
        zlo += __shfl_xor_sync(0xffffffffu, zlo, 1);
        zlo += __shfl_xor_sync(0xffffffffu, zlo, 2);
        zhi += __shfl_xor_sync(0xffffffffu, zhi, 1);
        zhi += __shfl_xor_sync(0xffffffffu, zhi, 2);

        if ((lane & 3) == 0) {
            long rlo = (long)tile * TILE_M + r0 + (lane >> 2);
            long rhi = rlo + 8;
            if (rlo < BN) {
                float z = zlo + bV0;
                g_s[rlo] = __fdividef(1.0f, 1.0f + __expf(-z));
            }
            if (rhi < BN) {
                float z = zhi + bV0;
                g_s[rhi] = __fdividef(1.0f, 1.0f + __expf(-z));
            }
        }
        __syncthreads();   // all reads of A done before next tile overwrites
    }
}

// ============================================================================
// Pass 2: one warp per (b,n). All 14 gather loads (7 values rows + 7 scores)
// issued up front for max MLP (kernel is latency-bound, nothing saturated).
// Lane l owns channels 4l..4l+3.
// ============================================================================
__global__ __launch_bounds__(256)
void pass2_kernel(const float* __restrict__ values, const int* __restrict__ neigh,
                  float* __restrict__ ctx, float* __restrict__ score,
                  int BN, int N)
{
    int gw = blockIdx.x * 8 + (threadIdx.x >> 5);
    if (gw >= BN) return;
    const int lane = threadIdx.x & 31;
    const int b = gw / N;
    const int n = gw - b * N;

    const int* nb = neigh + (long)n * KNB;
    int ix[KNB];
    #pragma unroll
    for (int k = 0; k < KNB; k++) ix[k] = __ldg(nb + k);

    // Issue the long-latency gathers first, all independent.
    const float* vb = values + (long)b * N * CDIM;
    float4 v4[KNB];
    #pragma unroll
    for (int k = 0; k < KNB; k++)
        v4[k] = *(const float4*)(vb + (long)ix[k] * CDIM + 4 * lane);

    float sk[KNB];
    #pragma unroll
    for (int k = 0; k < KNB; k++) sk[k] = g_s[b * N + ix[k]];

    float sum = 0.f;
    #pragma unroll
    for (int k = 0; k < KNB; k++) sum += sk[k];
    float inv = __fdividef(1.0f, sum);

    // score output is the raw sigmoid (pre-normalization), per reference.
    if (lane < KNB) score[(long)gw * KNB + lane] = sk[lane];

    float4 a = make_float4(0.f, 0.f, 0.f, 0.f);
    #pragma unroll
    for (int k = 0; k < KNB; k++) {
        float w = sk[k] * inv;
        a.x += w * v4[k].x; a.y += w * v4[k].y;
        a.z += w * v4[k].z; a.w += w * v4[k].w;
    }
    *(float4*)(ctx + (long)gw * CDIM + 4 * lane) = a;
}

// ============================================================================
// Launch
// ============================================================================
extern "C" void kernel_launch(void* const* d_in, const int* in_sizes, int n_in,
                              void* d_out, int out_size)
{
    const float* query  = (const float*)d_in[0];
    const float* values = (const float*)d_in[1];
    const int*   neigh  = (const int*)d_in[2];
    const float* W1     = (const float*)d_in[3];
    const float* b1     = (const float*)d_in[4];
    const float* Vw     = (const float*)d_in[5];
    const float* bV     = (const float*)d_in[6];

    const int BN = in_sizes[0] / CDIM;   // B*N
    const int N  = in_sizes[2] / KNB;    // nodes

    float* ctx   = (float*)d_out;
    float* score = (float*)d_out + (size_t)BN * CDIM;

    int nsm = 148;
    cudaDeviceGetAttribute(&nsm, cudaDevAttrMultiProcessorCount, 0);

    cudaFuncSetAttribute(pass1_hmma, cudaFuncAttributeMaxDynamicSharedMemorySize, SMEM_TOTAL);
    pass1_hmma<<<2 * nsm, P1_THREADS, SMEM_TOTAL>>>(query, W1, b1, Vw, bV, BN);

    int p2_blocks = (BN + 7) / 8;
    pass2_kernel<<<p2_blocks, 256>>>(values, neigh, ctx, score, BN, N);
}